// round 6
// baseline (speedup 1.0000x reference)
#include <cuda_runtime.h>
#include <cstdint>

typedef unsigned long long ull;

#define SEQ   512
#define BATCH 64
#define DIN   256
#define HID   1024
#define SBH   (SEQ*BATCH*HID)

// ---------------- persistent-kernel geometry ----------------
#define NBLK 128          // 64 j-tiles x 2 batch-groups, 1 block/SM
#define GRP  64           // blocks per barrier group (independent halves)
#define BT   32           // batch rows per block
#define JT   16           // hidden cols per block
#define HSP  1028         // hs row stride (floats): 1028*4B -> row r starts at bank group r mod 8
#define PS_ULL 4104       // W plane stride in ull (64B skew between the two j-planes)
#define RSP  528          // reduction slice stride (floats)
#define NCHUNK 4          // k staging chunks (256 k each)

#define OFF_MBAR 0                         // 4 mbarriers * 8B
#define OFF_W    128
#define OFF_H    (OFF_W + 2*PS_ULL*8)      // 128 + 65664 = 65792
#define SMEM_BYTES (OFF_H + BT*HSP*4)      // + 131584 = 197376  (red aliases hs)

// ---------------- device state ----------------
__device__ float g_h[2][BATCH*HID];   // ping-pong hidden state (L2-resident)
__device__ unsigned g_flags[NBLK];    // per-block step flags (barrier)

// ---------------- f32x2 helpers ----------------
__device__ __forceinline__ ull ffma2(ull a, ull b, ull c) {
    ull d; asm("fma.rn.f32x2 %0, %1, %2, %3;" : "=l"(d) : "l"(a), "l"(b), "l"(c)); return d;
}
__device__ __forceinline__ ull pk2(float x, float y) {
    ull r; asm("mov.b64 %0, {%1, %2};" : "=l"(r) : "f"(x), "f"(y)); return r;
}
__device__ __forceinline__ float2 upk(ull v) {
    float2 r; asm("mov.b64 {%0, %1}, %2;" : "=f"(r.x), "=f"(r.y) : "l"(v)); return r;
}

// ---------------- init: h0 = 0, flags = 0 ----------------
__global__ void init_kernel() {
    int i = blockIdx.x * blockDim.x + threadIdx.x;
    if (i < BATCH*HID) g_h[0][i] = 0.0f;
    if (i < NBLK) g_flags[i] = 0u;
}

// ---------------- phase 1: xp = x @ W_in^T + bias (into d_out) ----------------
#define P1_BM 128
#define P1_BN 64
#define P1_BK 16

__global__ __launch_bounds__(256) void xproj_kernel(
        const float* __restrict__ x, const float* __restrict__ Win,
        const float* __restrict__ bias, float* __restrict__ out) {
    __shared__ ull As[P1_BM][9];
    __shared__ ull Bs[P1_BN][9];

    const int t  = threadIdx.x;
    const int m0 = blockIdx.y * P1_BM;
    const int n0 = blockIdx.x * P1_BN;
    const int tm = t >> 4;
    const int tn = t & 15;

    ull acc[8][4];
    #pragma unroll
    for (int i = 0; i < 8; i++)
        #pragma unroll
        for (int j = 0; j < 4; j++) acc[i][j] = 0ull;

    for (int k0 = 0; k0 < DIN; k0 += P1_BK) {
        #pragma unroll
        for (int l = 0; l < 2; l++) {
            int idx = t + l * 256;
            int r = idx >> 2, c = idx & 3;
            float4 v = *reinterpret_cast<const float4*>(x + (size_t)(m0 + r) * DIN + k0 + c * 4);
            As[r][c*2]   = pk2(v.x, v.y);
            As[r][c*2+1] = pk2(v.z, v.w);
        }
        {
            int r = t >> 2, c = t & 3;
            float4 v = *reinterpret_cast<const float4*>(Win + (size_t)(n0 + r) * DIN + k0 + c * 4);
            Bs[r][c*2]   = pk2(v.x, v.y);
            Bs[r][c*2+1] = pk2(v.z, v.w);
        }
        __syncthreads();
        #pragma unroll
        for (int kp = 0; kp < 8; kp++) {
            ull a[8], b[4];
            #pragma unroll
            for (int i = 0; i < 8; i++) a[i] = As[tm + 16*i][kp];
            #pragma unroll
            for (int j = 0; j < 4; j++) b[j] = Bs[tn + 16*j][kp];
            #pragma unroll
            for (int i = 0; i < 8; i++)
                #pragma unroll
                for (int j = 0; j < 4; j++)
                    acc[i][j] = ffma2(a[i], b[j], acc[i][j]);
        }
        __syncthreads();
    }
    #pragma unroll
    for (int i = 0; i < 8; i++) {
        int m = m0 + tm + 16*i;
        #pragma unroll
        for (int j = 0; j < 4; j++) {
            int n = n0 + tn + 16*j;
            float2 s = upk(acc[i][j]);
            out[(size_t)m * HID + n] = s.x + s.y + bias[n];
        }
    }
}

// ---------------- mbarrier / staging helpers ----------------
__device__ __forceinline__ void mbar_wait(uint32_t mbar, uint32_t parity) {
    uint32_t done;
    do {
        asm volatile(
            "{\n\t.reg .pred p;\n\t"
            "mbarrier.try_wait.parity.acquire.cta.shared::cta.b64 p, [%1], %2, 0x989680;\n\t"
            "selp.b32 %0, 1, 0, p;\n\t}"
            : "=r"(done) : "r"(mbar), "r"(parity) : "memory");
    } while (!done);
}

// 4 k-chunks of 256 k; lane l copies row l's 1KB slice of each chunk.
__device__ __forceinline__ void stage_issue(uint32_t mbar0, uint32_t hs_sm,
                                            const float* srcbase, int t) {
    if (t < 32) {
        if (t == 0) {
            #pragma unroll
            for (int c = 0; c < NCHUNK; c++)
                asm volatile("mbarrier.arrive.expect_tx.shared.b64 _, [%0], %1;"
                             :: "r"(mbar0 + 8*c), "r"(32768u) : "memory");
        }
        __syncwarp();
        const char* src = (const char*)srcbase + (size_t)t * (HID*4);
        uint32_t dst = hs_sm + (uint32_t)t * (HSP*4);
        #pragma unroll
        for (int c = 0; c < NCHUNK; c++)
            asm volatile(
                "cp.async.bulk.shared::cluster.global.mbarrier::complete_tx::bytes [%0], [%1], %2, [%3];"
                :: "r"(dst + c*1024), "l"(src + c*1024), "r"(1024u), "r"(mbar0 + 8*c) : "memory");
    }
}

// ---------------- phase 2: persistent recurrent kernel ----------------
__global__ __launch_bounds__(256, 1) void rnn_kernel(
        const float* __restrict__ Whh, const float* __restrict__ alpha,
        float* __restrict__ out, int write_hn) {
    extern __shared__ char sm[];
    const uint32_t smb = (uint32_t)__cvta_generic_to_shared(sm);
    ull*   Wp  = reinterpret_cast<ull*>(sm + OFF_W);
    float* hs  = reinterpret_cast<float*>(sm + OFF_H);
    float* red = hs;                            // aliases hs (safe: h_prev lives in regs)
    const uint32_t mbar0 = smb + OFF_MBAR;
    const uint32_t hs_sm = smb + OFF_H;

    const int t   = threadIdx.x;
    const int bid = blockIdx.x;
    const int jtb = bid & 63;
    const int grp = bid >> 6;
    const int j0  = jtb * JT;
    const int b0g = grp * BT;

    if (t < NCHUNK)
        asm volatile("mbarrier.init.shared.b64 [%0], 1;" :: "r"(mbar0 + 8*t) : "memory");
    __syncthreads();

    // kick off staging of h0 while we load W
    stage_issue(mbar0, hs_sm, g_h[0] + (size_t)b0g * HID, t);

    // W planes with per-kp j-slot rotation: actual jj stored at slot (jj + 2*((kp>>2)&3)) & 7.
    // Readers (lane qp) see (kp>>2)&3 == qp, so the rotation puts the 8 (b,qp) addresses of
    // each W load wavefront into 8 distinct bank groups.
    #pragma unroll
    for (int l = 0; l < 32; l++) {
        int idx = t + l * 256;             // 0..8191
        int jl  = idx >> 9;                // 0..15
        int kp  = idx & 511;               // coalesced along kp
        float2 v = *reinterpret_cast<const float2*>(Whh + (size_t)(j0 + jl) * HID + 2 * kp);
        int slot = ((jl & 7) + 2 * ((kp >> 2) & 3)) & 7;
        Wp[(jl >> 3) * PS_ULL + kp * 8 + slot] = pk2(v.x, v.y);
    }

    // compute mapping: lane = (qp, b, a); thread tile = 8 rows (a+4m) x 8 j (plane b)
    // lane's k set: k = 128w + 8qp + 4(it&1) + 32(it>>1) + {0..3}, it = 0..7 (Kt = 32)
    const int w   = t >> 5;                // warp 0..7
    const int l   = t & 31;
    const int qp  = l >> 3;                // sub-slice 0..3
    const int b   = (l >> 2) & 1;          // j half (plane)
    const int a   = l & 3;                 // row offset: rows a+4m
    const int s_idx = 4 * w + qp;          // slice id 0..31
    const int chunk = w >> 1;              // staging chunk this warp consumes

    const float* hb = hs + a * HSP + 128 * w + 8 * qp;
    const ull*   wb = Wp + b * PS_ULL + (size_t)(64 * w + 4 * qp) * 8;
    int wOff[4];
    #pragma unroll
    for (int p = 0; p < 4; p++) wOff[p] = 2 * ((p + qp) & 3);
    float* redw = red + s_idx * RSP + a * 16 + 8 * b;

    // epilogue mapping: 2 outputs per thread, h_prev in registers
    const int re = t >> 3;                 // batch row 0..31
    const int jp = (t & 7) * 2;            // j pair 0..14
    const float al0 = alpha[j0 + jp];
    const float al1 = alpha[j0 + jp + 1];
    const size_t hrow = (size_t)(b0g + re) * HID + j0 + jp;
    float hp0 = 0.0f, hp1 = 0.0f;

    __syncthreads();   // W planes ready

    for (int step = 0; step < SEQ; step++) {
        // prefetch xp (global) before waiting on staged h
        const size_t oidx = (size_t)step * (BATCH*HID) + hrow;
        float2 xpv = *reinterpret_cast<const float2*>(out + oidx);

        mbar_wait(mbar0 + 8 * chunk, step & 1);

        ull acc[8][8];
        #pragma unroll
        for (int m = 0; m < 8; m++)
            #pragma unroll
            for (int j = 0; j < 8; j++) acc[m][j] = 0ull;

        #pragma unroll 1
        for (int it = 0; it < 8; it++) {
            const int ho = 4 * (it & 1) + 32 * (it >> 1);   // float offset; ull row offset = 4*ho
            const float* hq = hb + ho;
            ulonglong2 Hv[8];
            #pragma unroll
            for (int m = 0; m < 8; m++)
                Hv[m] = *reinterpret_cast<const ulonglong2*>(hq + m * (4 * HSP));
            const ull* wr = wb + 4 * ho;                     // kp row
            #pragma unroll
            for (int p = 0; p < 4; p++) {
                ulonglong2 u = *reinterpret_cast<const ulonglong2*>(wr + wOff[p]);
                #pragma unroll
                for (int m = 0; m < 8; m++) {
                    acc[m][2*p]   = ffma2(Hv[m].x, u.x, acc[m][2*p]);
                    acc[m][2*p+1] = ffma2(Hv[m].x, u.y, acc[m][2*p+1]);
                }
            }
            #pragma unroll
            for (int p = 0; p < 4; p++) {
                ulonglong2 u = *reinterpret_cast<const ulonglong2*>(wr + 8 + wOff[p]);
                #pragma unroll
                for (int m = 0; m < 8; m++) {
                    acc[m][2*p]   = ffma2(Hv[m].y, u.x, acc[m][2*p]);
                    acc[m][2*p+1] = ffma2(Hv[m].y, u.y, acc[m][2*p+1]);
                }
            }
        }

        __syncthreads();   // all warps done reading hs -> red may overwrite it

        // fold f32x2 and store partials: red[s][(a+4m)*16 + 8b + 0..7]
        #pragma unroll
        for (int m = 0; m < 8; m++) {
            float2 f0 = upk(acc[m][0]), f1 = upk(acc[m][1]);
            float2 f2 = upk(acc[m][2]), f3 = upk(acc[m][3]);
            float2 f4 = upk(acc[m][4]), f5 = upk(acc[m][5]);
            float2 f6 = upk(acc[m][6]), f7 = upk(acc[m][7]);
            float4 v0 = make_float4(f0.x+f0.y, f1.x+f1.y, f2.x+f2.y, f3.x+f3.y);
            float4 v1 = make_float4(f4.x+f4.y, f5.x+f5.y, f6.x+f6.y, f7.x+f7.y);
            *reinterpret_cast<float4*>(redw + 64 * m)     = v0;
            *reinterpret_cast<float4*>(redw + 64 * m + 4) = v1;
        }
        __syncthreads();

        // reduce 32 slices for this thread's 2 outputs
        float px0 = 0.f, px1 = 0.f, px2 = 0.f, px3 = 0.f;
        float py0 = 0.f, py1 = 0.f, py2 = 0.f, py3 = 0.f;
        #pragma unroll
        for (int sg = 0; sg < 8; sg++) {
            float2 r0 = *reinterpret_cast<const float2*>(red + (4*sg+0) * RSP + re * 16 + jp);
            float2 r1 = *reinterpret_cast<const float2*>(red + (4*sg+1) * RSP + re * 16 + jp);
            float2 r2 = *reinterpret_cast<const float2*>(red + (4*sg+2) * RSP + re * 16 + jp);
            float2 r3 = *reinterpret_cast<const float2*>(red + (4*sg+3) * RSP + re * 16 + jp);
            px0 += r0.x; py0 += r0.y;
            px1 += r1.x; py1 += r1.y;
            px2 += r2.x; py2 += r2.y;
            px3 += r3.x; py3 += r3.y;
        }
        float s0 = (px0 + px1) + (px2 + px3);
        float s1 = (py0 + py1) + (py2 + py3);

        // gate
        float ht0 = tanhf(xpv.x + s0);
        float ht1 = tanhf(xpv.y + s1);
        float hn0 = hp0 + al0 * (ht0 - hp0);
        float hn1 = hp1 + al1 * (ht1 - hp1);
        hp0 = hn0; hp1 = hn1;

        float* hnxt = g_h[(step + 1) & 1];
        *reinterpret_cast<float2*>(hnxt + hrow) = make_float2(hn0, hn1);
        *reinterpret_cast<float2*>(out + oidx)  = make_float2(hn0, hn1);
        if (write_hn && step == SEQ - 1)
            *reinterpret_cast<float2*>(out + (size_t)SBH + hrow) = make_float2(hn0, hn1);

        if (step < SEQ - 1) {
            __syncthreads();
            if (t == 0) {
                __threadfence();
                asm volatile("st.volatile.global.u32 [%0], %1;"
                             :: "l"(g_flags + bid), "r"((unsigned)(step + 1)) : "memory");
            }
            if (t < 32) {
                const uint4* fp = reinterpret_cast<const uint4*>(g_flags + grp * GRP);
                const unsigned tgt = (unsigned)(step + 1);
                bool mine = true;
                while (true) {
                    if (t < 16) {
                        unsigned fx, fy, fz, fw;
                        asm volatile("ld.volatile.global.v4.u32 {%0,%1,%2,%3}, [%4];"
                                     : "=r"(fx), "=r"(fy), "=r"(fz), "=r"(fw)
                                     : "l"(fp + t) : "memory");
                        mine = (fx >= tgt) && (fy >= tgt) && (fz >= tgt) && (fw >= tgt);
                    }
                    if (__all_sync(0xffffffffu, mine)) break;
                }
                __threadfence();
            }
            __syncthreads();
            stage_issue(mbar0, hs_sm, hnxt + (size_t)b0g * HID, t);
        }
    }
}

// ---------------- launch ----------------
extern "C" void kernel_launch(void* const* d_in, const int* in_sizes, int n_in,
                              void* d_out, int out_size) {
    const float* x     = (const float*)d_in[0];   // [512,64,256]
    const float* W_in  = (const float*)d_in[1];   // [1024,256]
    const float* W_hh  = (const float*)d_in[2];   // [1024,1024]
    const float* bias  = (const float*)d_in[3];   // [1024]
    const float* alpha = (const float*)d_in[4];   // [1024]
    float* out = (float*)d_out;

    cudaFuncSetAttribute(rnn_kernel, cudaFuncAttributeMaxDynamicSharedMemorySize, SMEM_BYTES);

    init_kernel<<<(BATCH*HID + 255) / 256, 256>>>();

    dim3 g1(HID / P1_BN, (SEQ * BATCH) / P1_BM);
    xproj_kernel<<<g1, 256>>>(x, W_in, bias, out);

    int write_hn = (out_size >= SBH + BATCH * HID) ? 1 : 0;
    rnn_kernel<<<NBLK, 256, SMEM_BYTES>>>(W_hh, alpha, out, write_hn);
}

// round 8
// speedup vs baseline: 1.1197x; 1.1197x over previous
#include <cuda_runtime.h>
#include <cstdint>

typedef unsigned long long ull;

#define SEQ   512
#define BATCH 64
#define DIN   256
#define HID   1024
#define SBH   (SEQ*BATCH*HID)

// ---------------- persistent-kernel geometry ----------------
#define NBLK 128          // 64 j-tiles x 2 batch-groups, 1 block/SM
#define GRP  64           // blocks per batch group
#define BT   32           // batch rows per block
#define JT   16           // hidden cols per block
#define WSP  18           // Ws2 stride (ull) per k-pair (R2 layout, proven conflict-free)
#define RSP  520          // reduction slice stride (floats)
#define HROW 260          // chunk row stride (floats): 260%32=4 -> 8 q-rows spread bank groups
#define CSLOT (BT*HROW)   // floats per k-chunk buffer (32 rows x 256k +pad)
#define NCHUNK 4

#define OFF_MBAR 0                           // 4 mbarriers
#define OFF_W    128
#define OFF_RED  (OFF_W + 512*WSP*8)         // 128 + 73728 = 73856
#define OFF_H    (OFF_RED + 8*RSP*4)         // + 16640 = 90496
#define SMEM_BYTES (OFF_H + NCHUNK*CSLOT*4)  // + 133120 = 223616

// ---------------- device state ----------------
__device__ float g_h[2][BATCH*HID];   // ping-pong hidden state (L2-resident)
__device__ unsigned g_flags[NBLK];    // per-block completed-step counters

// ---------------- f32x2 helpers ----------------
__device__ __forceinline__ ull ffma2(ull a, ull b, ull c) {
    ull d; asm("fma.rn.f32x2 %0, %1, %2, %3;" : "=l"(d) : "l"(a), "l"(b), "l"(c)); return d;
}
__device__ __forceinline__ ull pk2(float x, float y) {
    ull r; asm("mov.b64 %0, {%1, %2};" : "=l"(r) : "f"(x), "f"(y)); return r;
}
__device__ __forceinline__ float2 upk(ull v) {
    float2 r; asm("mov.b64 {%0, %1}, %2;" : "=f"(r.x), "=f"(r.y) : "l"(v)); return r;
}

// ---------------- init: h0 = 0, flags = 0 ----------------
__global__ void init_kernel() {
    int i = blockIdx.x * blockDim.x + threadIdx.x;
    if (i < BATCH*HID) g_h[0][i] = 0.0f;
    if (i < NBLK) g_flags[i] = 0u;
}

// ---------------- phase 1: xp = x @ W_in^T + bias (into d_out) ----------------
#define P1_BM 128
#define P1_BN 64
#define P1_BK 16

__global__ __launch_bounds__(256) void xproj_kernel(
        const float* __restrict__ x, const float* __restrict__ Win,
        const float* __restrict__ bias, float* __restrict__ out) {
    __shared__ ull As[P1_BM][9];
    __shared__ ull Bs[P1_BN][9];

    const int t  = threadIdx.x;
    const int m0 = blockIdx.y * P1_BM;
    const int n0 = blockIdx.x * P1_BN;
    const int tm = t >> 4;
    const int tn = t & 15;

    ull acc[8][4];
    #pragma unroll
    for (int i = 0; i < 8; i++)
        #pragma unroll
        for (int j = 0; j < 4; j++) acc[i][j] = 0ull;

    for (int k0 = 0; k0 < DIN; k0 += P1_BK) {
        #pragma unroll
        for (int l = 0; l < 2; l++) {
            int idx = t + l * 256;
            int r = idx >> 2, c = idx & 3;
            float4 v = *reinterpret_cast<const float4*>(x + (size_t)(m0 + r) * DIN + k0 + c * 4);
            As[r][c*2]   = pk2(v.x, v.y);
            As[r][c*2+1] = pk2(v.z, v.w);
        }
        {
            int r = t >> 2, c = t & 3;
            float4 v = *reinterpret_cast<const float4*>(Win + (size_t)(n0 + r) * DIN + k0 + c * 4);
            Bs[r][c*2]   = pk2(v.x, v.y);
            Bs[r][c*2+1] = pk2(v.z, v.w);
        }
        __syncthreads();
        #pragma unroll
        for (int kp = 0; kp < 8; kp++) {
            ull a[8], b[4];
            #pragma unroll
            for (int i = 0; i < 8; i++) a[i] = As[tm + 16*i][kp];
            #pragma unroll
            for (int j = 0; j < 4; j++) b[j] = Bs[tn + 16*j][kp];
            #pragma unroll
            for (int i = 0; i < 8; i++)
                #pragma unroll
                for (int j = 0; j < 4; j++)
                    acc[i][j] = ffma2(a[i], b[j], acc[i][j]);
        }
        __syncthreads();
    }
    #pragma unroll
    for (int i = 0; i < 8; i++) {
        int m = m0 + tm + 16*i;
        #pragma unroll
        for (int j = 0; j < 4; j++) {
            int n = n0 + tn + 16*j;
            float2 s = upk(acc[i][j]);
            out[(size_t)m * HID + n] = s.x + s.y + bias[n];
        }
    }
}

// ---------------- mbarrier wait ----------------
__device__ __forceinline__ void mbar_wait(uint32_t mbar, uint32_t parity) {
    uint32_t done;
    do {
        asm volatile(
            "{\n\t.reg .pred p;\n\t"
            "mbarrier.try_wait.parity.acquire.cta.shared::cta.b64 p, [%1], %2, 0x989680;\n\t"
            "selp.b32 %0, 1, 0, p;\n\t}"
            : "=r"(done) : "r"(mbar), "r"(parity) : "memory");
    } while (!done);
}

// ---------------- phase 2: persistent recurrent kernel ----------------
__global__ __launch_bounds__(256, 1) void rnn_kernel(
        const float* __restrict__ Whh, const float* __restrict__ alpha,
        float* __restrict__ out, int write_hn) {
    extern __shared__ char sm[];
    const uint32_t smb = (uint32_t)__cvta_generic_to_shared(sm);
    ull*   Ws2 = reinterpret_cast<ull*>(sm + OFF_W);
    float* red = reinterpret_cast<float*>(sm + OFF_RED);
    float* hs  = reinterpret_cast<float*>(sm + OFF_H);
    const uint32_t mbar0 = smb + OFF_MBAR;
    const uint32_t hs_sm = smb + OFF_H;

    const int t   = threadIdx.x;
    const int bid = blockIdx.x;
    const int jtb = bid & 63;
    const int grp = bid >> 6;
    const int j0  = jtb * JT;
    const int b0g = grp * BT;

    if (t < NCHUNK)
        asm volatile("mbarrier.init.shared.b64 [%0], 1;" :: "r"(mbar0 + 8*t) : "memory");
    __syncthreads();

    // Load W_hh slice (R2 layout): Ws2[kp*WSP + jl] = {W[j0+jl][2kp], W[j0+jl][2kp+1]}
    #pragma unroll
    for (int l = 0; l < 32; l++) {
        int idx = t + l * 256;
        int jl  = idx >> 9;
        int kp  = idx & 511;
        float2 v = *reinterpret_cast<const float2*>(Whh + (size_t)(j0 + jl) * HID + 2 * kp);
        Ws2[kp * WSP + jl] = pk2(v.x, v.y);
    }

    // compute mapping: warp w = k-slice [128w,128w+128); lane -> (q rows, jt4 cols)
    const int w   = t >> 5;
    const int l   = t & 31;
    const int q   = l & 7;                 // rows q+8m
    const int jt4 = l >> 3;                // cols 4*jt4..+3
    const int mychunk = w >> 1;            // staged chunk this warp consumes

    // kp base for warp w is 64w, fully encoded here (NO extra half-offset in the loop)
    const ull*   wpB = Ws2 + (size_t)w * 64 * WSP + 4 * jt4;
    const float* hqB = hs + mychunk * CSLOT + q * HROW + 128 * (w & 1);

    // epilogue mapping: 2 outputs per thread, h_prev in registers
    const int re = t >> 3;
    const int jp = (t & 7) * 2;
    const float al0 = alpha[j0 + jp];
    const float al1 = alpha[j0 + jp + 1];
    const size_t hrow = (size_t)(b0g + re) * HID + j0 + jp;
    float hp0 = 0.0f, hp1 = 0.0f;

    __syncthreads();   // Ws2 ready

    for (int step = 0; step < SEQ; step++) {
        // prefetch xp (L2/DRAM) before any waiting
        const size_t oidx = (size_t)step * (BATCH*HID) + hrow;
        float2 xpv = *reinterpret_cast<const float2*>(out + oidx);

        // ---- stager warp (7): gate each chunk on its 16 producer blocks, then bulk-copy ----
        if (w == 7) {
            const float* hcur = g_h[step & 1] + (size_t)b0g * HID;
            const unsigned tgt = (unsigned)step;
            #pragma unroll
            for (int c = 0; c < NCHUNK; c++) {
                const unsigned* fb = g_flags + grp * GRP + 16 * c;
                bool ok = true;
                if (l < 16) {
                    unsigned f;
                    asm volatile("ld.acquire.gpu.global.u32 %0, [%1];" : "=r"(f) : "l"(fb + l) : "memory");
                    ok = (f >= tgt);
                }
                while (!__all_sync(0xffffffffu, ok)) {
                    __nanosleep(32);
                    if (l < 16) {
                        unsigned f;
                        asm volatile("ld.acquire.gpu.global.u32 %0, [%1];" : "=r"(f) : "l"(fb + l) : "memory");
                        ok = (f >= tgt);
                    }
                }
                if (l == 0)
                    asm volatile("mbarrier.arrive.expect_tx.shared.b64 _, [%0], %1;"
                                 :: "r"(mbar0 + 8*c), "r"(32768u) : "memory");
                __syncwarp();
                const char* src = (const char*)(hcur + (size_t)l * HID + c * 256);
                uint32_t dst = hs_sm + (uint32_t)(c * CSLOT + l * HROW) * 4u;
                asm volatile(
                    "cp.async.bulk.shared::cluster.global.mbarrier::complete_tx::bytes [%0], [%1], %2, [%3];"
                    :: "r"(dst), "l"(src), "r"(1024u), "r"(mbar0 + 8*c) : "memory");
            }
        }

        mbar_wait(mbar0 + 8 * mychunk, step & 1);

        // ---- compute: acc[4 rows][4 cols] over 128 k ----
        ull acc[4][4];
        #pragma unroll
        for (int m = 0; m < 4; m++)
            #pragma unroll
            for (int j = 0; j < 4; j++) acc[m][j] = 0ull;

        #pragma unroll 8
        for (int kq = 0; kq < 32; kq++) {
            const ull* w0 = wpB + (size_t)(2 * kq) * WSP;
            const ull* w1 = w0 + WSP;
            ulonglong2 W00 = *reinterpret_cast<const ulonglong2*>(w0);
            ulonglong2 W01 = *reinterpret_cast<const ulonglong2*>(w0 + 2);
            ulonglong2 W10 = *reinterpret_cast<const ulonglong2*>(w1);
            ulonglong2 W11 = *reinterpret_cast<const ulonglong2*>(w1 + 2);
            const float* hk = hqB + 4 * kq;
            #pragma unroll
            for (int m = 0; m < 4; m++) {
                ulonglong2 Hm = *reinterpret_cast<const ulonglong2*>(hk + m * (8 * HROW));
                acc[m][0] = ffma2(Hm.x, W00.x, acc[m][0]);
                acc[m][0] = ffma2(Hm.y, W10.x, acc[m][0]);
                acc[m][1] = ffma2(Hm.x, W00.y, acc[m][1]);
                acc[m][1] = ffma2(Hm.y, W10.y, acc[m][1]);
                acc[m][2] = ffma2(Hm.x, W01.x, acc[m][2]);
                acc[m][2] = ffma2(Hm.y, W11.x, acc[m][2]);
                acc[m][3] = ffma2(Hm.x, W01.y, acc[m][3]);
                acc[m][3] = ffma2(Hm.y, W11.y, acc[m][3]);
            }
        }

        // ---- per-warp partials -> red ----
        #pragma unroll
        for (int m = 0; m < 4; m++) {
            float2 p0 = upk(acc[m][0]);
            float2 p1 = upk(acc[m][1]);
            float2 p2 = upk(acc[m][2]);
            float2 p3 = upk(acc[m][3]);
            float4 v = make_float4(p0.x + p0.y, p1.x + p1.y, p2.x + p2.y, p3.x + p3.y);
            *reinterpret_cast<float4*>(red + w * RSP + (q + 8 * m) * 16 + 4 * jt4) = v;
        }
        __syncthreads();

        // ---- reduce 8 k-slices for this thread's 2 outputs ----
        float s0 = 0.f, s1 = 0.f;
        #pragma unroll
        for (int ww = 0; ww < 8; ww++) {
            float2 rv = *reinterpret_cast<const float2*>(red + ww * RSP + 2 * t);
            s0 += rv.x; s1 += rv.y;
        }

        // ---- gate + stores ----
        float ht0 = tanhf(xpv.x + s0);
        float ht1 = tanhf(xpv.y + s1);
        float hn0 = hp0 + al0 * (ht0 - hp0);
        float hn1 = hp1 + al1 * (ht1 - hp1);
        hp0 = hn0; hp1 = hn1;

        float* hnxt = g_h[(step + 1) & 1];
        *reinterpret_cast<float2*>(hnxt + hrow) = make_float2(hn0, hn1);
        *reinterpret_cast<float2*>(out + oidx)  = make_float2(hn0, hn1);
        if (write_hn && step == SEQ - 1)
            *reinterpret_cast<float2*>(out + (size_t)SBH + hrow) = make_float2(hn0, hn1);

        __syncthreads();   // all stores + all red reads done

        if (step < SEQ - 1 && t == 0) {
            __threadfence();
            asm volatile("st.release.gpu.global.u32 [%0], %1;"
                         :: "l"(g_flags + bid), "r"((unsigned)(step + 1)) : "memory");
        }
    }
}

// ---------------- launch ----------------
extern "C" void kernel_launch(void* const* d_in, const int* in_sizes, int n_in,
                              void* d_out, int out_size) {
    const float* x     = (const float*)d_in[0];   // [512,64,256]
    const float* W_in  = (const float*)d_in[1];   // [1024,256]
    const float* W_hh  = (const float*)d_in[2];   // [1024,1024]
    const float* bias  = (const float*)d_in[3];   // [1024]
    const float* alpha = (const float*)d_in[4];   // [1024]
    float* out = (float*)d_out;

    cudaFuncSetAttribute(rnn_kernel, cudaFuncAttributeMaxDynamicSharedMemorySize, SMEM_BYTES);

    init_kernel<<<(BATCH*HID + 255) / 256, 256>>>();

    dim3 g1(HID / P1_BN, (SEQ * BATCH) / P1_BM);
    xproj_kernel<<<g1, 256>>>(x, W_in, bias, out);

    int write_hn = (out_size >= SBH + BATCH * HID) ? 1 : 0;
    rnn_kernel<<<NBLK, 256, SMEM_BYTES>>>(W_hh, alpha, out, write_hn);
}